// round 16
// baseline (speedup 1.0000x reference)
#include <cuda_runtime.h>
#include <cuda_fp16.h>
#include <math.h>
#include <stdint.h>

#define NN 100000
#define NE 1600000
#define NF 512
#define FD 128
#define NC 10
#define OUTC 12

// ================= PTX helpers (sm_80-compatible only) =================
__device__ __forceinline__ uint32_t s2u(const void* p) {
    uint32_t a;
    asm("{ .reg .u64 t; cvta.to.shared.u64 t, %1; cvt.u32.u64 %0, t; }"
        : "=r"(a) : "l"(p));
    return a;
}
__device__ __forceinline__ void cpa16(uint32_t dst, const void* src) {
    asm volatile("cp.async.cg.shared.global [%0], [%1], 16;" :: "r"(dst), "l"(src));
}
#define CP_COMMIT() asm volatile("cp.async.commit_group;" ::: "memory")
#define CP_WAIT1()  asm volatile("cp.async.wait_group 1;" ::: "memory")
#define CP_WAIT3()  asm volatile("cp.async.wait_group 3;" ::: "memory")
#define CP_WAIT0()  asm volatile("cp.async.wait_group 0;" ::: "memory")

__device__ __forceinline__ void ldsm4(uint32_t* r, uint32_t addr) {
    asm volatile("ldmatrix.sync.aligned.m8n8.x4.shared.b16 {%0,%1,%2,%3}, [%4];"
                 : "=r"(r[0]), "=r"(r[1]), "=r"(r[2]), "=r"(r[3]) : "r"(addr));
}
__device__ __forceinline__ void mma16816h(float* c, const uint32_t* a, const uint32_t* b) {
    asm volatile("mma.sync.aligned.m16n8k16.row.col.f32.f16.f16.f32 "
                 "{%0,%1,%2,%3}, {%4,%5,%6,%7}, {%8,%9}, {%0,%1,%2,%3};"
                 : "+f"(c[0]), "+f"(c[1]), "+f"(c[2]), "+f"(c[3])
                 : "r"(a[0]), "r"(a[1]), "r"(a[2]), "r"(a[3]), "r"(b[0]), "r"(b[1]));
}

// ================= scratch (device globals) =================
__device__ __half g_Hh [(size_t)NN * FD];
__device__ __half g_P1 [(size_t)2 * NN * FD];   // layer1 agg out; later W3 GEMM out
__device__ __half g_Gh [(size_t)2 * NN * FD];
__device__ __half g_P2 [(size_t)2 * NN * FD];
__device__ __half g_P3 [(size_t)NN * FD];
__device__ __half g_P4 [(size_t)NN * FD];
__device__ __half g_Th [(size_t)NN * FD];
__device__ float g_C10[(size_t)NN * NC];
#define WOFF_W1 0
#define WOFF_W2 (128 * 512)
#define WOFF_W3 (WOFF_W2 + 128 * 128)
#define WOFF_M1 (WOFF_W3 + 128 * 128)
#define WOFF_M2 (WOFF_M1 + 128 * 128)
#define WOFF_WD (WOFF_M2 + 128 * 128)
#define WTOT    (WOFF_WD + 128 * 128)
__device__ __half g_Wf[WTOT];
__device__ int   g_cnt [2 * NN];
__device__ float g_dis [2 * NN];
__device__ float g_invd[2 * NN];
__device__ int   g_off [2 * (NN + 1)];
__device__ int   g_cur [2 * NN];
__device__ int   g_btot[2 * 128];
__device__ int   g_ssrc[2 * NE];
__device__ int   g_ssrcp[NE];
__device__ float g_sw  [2 * NE];

// ================= CSR build (merged kernels) =================
__global__ void k_count2(const int* __restrict__ d0, const int* __restrict__ d1,
                         int* __restrict__ cnt) {
    int i = blockIdx.x * blockDim.x + threadIdx.x;
    if (i < NE) atomicAdd(&cnt[d0[i]], 1);
    else {
        int j = i - NE;
        if (j < NE) atomicAdd(&cnt[NN + d1[j]], 1);
    }
}

__global__ void k_deg2(const int* __restrict__ cnt, float* __restrict__ dis,
                       float* __restrict__ invd) {
    int i = blockIdx.x * blockDim.x + threadIdx.x;
    if (i < 2 * NN) {
        float d = (float)(cnt[i] + 1);
        dis[i]  = rsqrtf(d);
        invd[i] = 1.0f / d;
    }
}

#define SCB 1024
#define NB  ((NN + SCB - 1) / SCB)
__global__ void k_scan_blk2(const int* __restrict__ cnt, int* __restrict__ off,
                            int* __restrict__ btot) {
    __shared__ int ws[32];
    const unsigned FULL = 0xffffffffu;
    int g = blockIdx.x / NB, b = blockIdx.x % NB;
    const int* c = cnt + g * NN;
    int* o  = off + g * (NN + 1);
    int* bt = btot + g * 128;
    int t = threadIdx.x, w = t >> 5, l = t & 31;
    int i = b * SCB + t;
    int v = (i < NN) ? c[i] : 0;
    int s = v;
    #pragma unroll
    for (int d = 1; d < 32; d <<= 1) {
        int oo = __shfl_up_sync(FULL, s, d);
        if (l >= d) s += oo;
    }
    if (l == 31) ws[w] = s;
    __syncthreads();
    if (w == 0) {
        int x2 = ws[l];
        #pragma unroll
        for (int d = 1; d < 32; d <<= 1) {
            int oo = __shfl_up_sync(FULL, x2, d);
            if (l >= d) x2 += oo;
        }
        ws[l] = x2;
    }
    __syncthreads();
    int incl = s + (w > 0 ? ws[w - 1] : 0);
    if (i < NN) o[i] = incl - v;
    if (t == SCB - 1) bt[b] = incl;
}

__global__ void k_scan_tot2(int* __restrict__ btot, int* __restrict__ off) {
    __shared__ int sh[128];
    int g = blockIdx.x;
    int* bt = btot + g * 128;
    int t = threadIdx.x;
    int v = (t < NB) ? bt[t] : 0;
    sh[t] = v;
    __syncthreads();
    #pragma unroll
    for (int d = 1; d < 128; d <<= 1) {
        int o = (t >= d) ? sh[t - d] : 0;
        __syncthreads();
        sh[t] += o;
        __syncthreads();
    }
    if (t < NB) bt[t] = sh[t] - v;
    if (t == 127) off[g * (NN + 1) + NN] = sh[127];
}

__global__ void k_scan_add2(int* __restrict__ off, const int* __restrict__ btot,
                            int* __restrict__ cur, int gpb) {
    int g = blockIdx.x / gpb;
    int i = (blockIdx.x % gpb) * blockDim.x + threadIdx.x;
    if (i < NN) {
        int e = off[g * (NN + 1) + i] + btot[g * 128 + (i >> 10)];
        off[g * (NN + 1) + i] = e;
        cur[g * NN + i] = e;
    }
}

__global__ void k_place2(const int* __restrict__ ei, const int* __restrict__ eh,
                         const float* __restrict__ dis, int* __restrict__ cur,
                         int* __restrict__ ssrc, float* __restrict__ sw,
                         const int* __restrict__ perm, int* __restrict__ ssrcp) {
    int gi = blockIdx.x * blockDim.x + threadIdx.x;
    if (gi < NE) {
        int s = ei[gi], d = ei[NE + gi];
        int p = atomicAdd(&cur[d], 1);
        ssrc[p]  = s;
        sw[p]    = dis[s] * dis[d];
        ssrcp[p] = perm[s];
    } else {
        int e = gi - NE;
        if (e < NE) {
            int s = eh[e], d = eh[NE + e];
            int p = atomicAdd(&cur[NN + d], 1);
            ssrc[NE + p] = s;
            sw[NE + p]   = dis[NN + s] * dis[NN + d];
        }
    }
}

// ================= weight prep =================
__global__ void k_prepw(const float* __restrict__ W, __half* __restrict__ Bt, int K) {
    int i = blockIdx.x * blockDim.x + threadIdx.x;
    if (i < K * 128) {
        int n = i / K, k = i - n * K;
        Bt[(size_t)n * K + k] = __float2half(W[(size_t)k * 128 + n]);
    }
}

__global__ void k_prepw5(const float* __restrict__ W2, const float* __restrict__ W3,
                         const float* __restrict__ M1, const float* __restrict__ M2,
                         const float* __restrict__ Wd, __half* __restrict__ Wf) {
    int i = blockIdx.x * blockDim.x + threadIdx.x;
    if (i >= 5 * 128 * 128) return;
    int r = i >> 14, j = i & 16383;
    const float* W = (r == 0) ? W2 : (r == 1) ? W3 : (r == 2) ? M1 : (r == 3) ? M2 : Wd;
    int woff = (r == 0) ? WOFF_W2 : (r == 1) ? WOFF_W3 : (r == 2) ? WOFF_M1
             : (r == 3) ? WOFF_M2 : WOFF_WD;
    int n = j >> 7, k = j & 127;
    Wf[woff + (size_t)n * 128 + k] = __float2half(W[(size_t)k * 128 + n]);
}

// ================= fp16 mma.sync GEMM =================
#define STRIDE_B 80
#define ARR_SZ   (128 * STRIDE_B)       // 10240
#define STAGE_SZ (2 * ARR_SZ)           // 20480 (A + B)
#define SMEM_SZ  (2 * STAGE_SZ)         // 40960

__device__ __forceinline__ void wmma_prefetch(
    uint32_t sbase, const __half* A, const __half* B,
    int m0, int M, int K, int k0, int tid)
{
    #pragma unroll
    for (int p = 0; p < 2; p++) {
        int idx = tid + p * 256;
        int row = idx >> 2, cg = idx & 3;
        int gr = m0 + row; if (gr >= M) gr = M - 1;
        size_t aoff = (size_t)gr * K + k0 + cg * 8;
        size_t boff = (size_t)row * K + k0 + cg * 8;
        uint32_t so = row * STRIDE_B + cg * 16;
        cpa16(sbase + 0 * ARR_SZ + so, A + aoff);
        cpa16(sbase + 1 * ARR_SZ + so, B + boff);
    }
}

#define WMMA_MAINLOOP_BODY(st)                                                   \
    {                                                                            \
        _Pragma("unroll")                                                        \
        for (int kk = 0; kk < 2; kk++) {                                         \
            const uint32_t kb = kk * 32;                                         \
            uint32_t ah[2][4], bh[4][4];                                         \
            _Pragma("unroll")                                                    \
            for (int mt = 0; mt < 2; mt++) {                                     \
                uint32_t ao = (st) + aoffs + mt * (16 * STRIDE_B) + kb;          \
                ldsm4(ah[mt], ao + 0 * ARR_SZ);                                  \
            }                                                                    \
            _Pragma("unroll")                                                    \
            for (int np = 0; np < 4; np++) {                                     \
                uint32_t bo = (st) + boffs + np * (16 * STRIDE_B) + kb;          \
                ldsm4(bh[np], bo + 1 * ARR_SZ);                                  \
            }                                                                    \
            _Pragma("unroll")                                                    \
            for (int mt = 0; mt < 2; mt++)                                       \
                _Pragma("unroll")                                                \
                for (int nt = 0; nt < 8; nt++)                                   \
                    mma16816h(c[mt][nt], ah[mt], &bh[nt >> 1][(nt & 1) * 2]);    \
        }                                                                        \
    }

#define WMMA_EPILOGUE()                                                          \
    _Pragma("unroll")                                                            \
    for (int mt = 0; mt < 2; mt++) {                                             \
        _Pragma("unroll")                                                        \
        for (int part = 0; part < 2; part++) {                                   \
            int gr = m0 + wm0 + mt * 16 + (lane >> 2) + part * 8;                \
            if (gr >= M) continue;                                               \
            _Pragma("unroll")                                                    \
            for (int nt = 0; nt < 8; nt++) {                                     \
                int gcol = wn0 + nt * 8 + (lane & 3) * 2;                        \
                float v0 = c[mt][nt][part * 2 + 0];                              \
                float v1 = c[mt][nt][part * 2 + 1];                              \
                if (bias) { v0 += bias[gcol]; v1 += bias[gcol + 1]; }            \
                if (dorelu) { v0 = fmaxf(v0, 0.f); v1 = fmaxf(v1, 0.f); }        \
                __half2 hh = __floats2half2_rn(v0, v1);                          \
                *(uint32_t*)(Chf + (size_t)gr * FD + gcol) = *(uint32_t*)&hh;    \
            }                                                                    \
        }                                                                        \
    }

__global__ void __launch_bounds__(256, 2) k_wmma(
    const __half* __restrict__ A, const __half* __restrict__ B,
    const float* __restrict__ bias, int dorelu,
    __half* __restrict__ Chf, int M, int K)
{
    extern __shared__ char smem[];
    const uint32_t sb = s2u(smem);
    const int tid  = threadIdx.x;
    const int lane = tid & 31, w = tid >> 5;
    const int wm0 = (w >> 1) * 32, wn0 = (w & 1) * 64;
    const int m0  = blockIdx.x * 128;

    float c[2][8][4];
    #pragma unroll
    for (int i = 0; i < 2; i++)
        #pragma unroll
        for (int j = 0; j < 8; j++)
            #pragma unroll
            for (int q = 0; q < 4; q++) c[i][j][q] = 0.f;

    const uint32_t aoffs = (uint32_t)((wm0 + (lane & 15)) * STRIDE_B + (lane >> 4) * 16);
    const uint32_t boffs = (uint32_t)((wn0 + ((lane >> 4) & 1) * 8 + (lane & 7)) * STRIDE_B
                                      + ((lane >> 3) & 1) * 16);

    const int nch = K >> 5;
    wmma_prefetch(sb, A, B, m0, M, K, 0, tid);
    CP_COMMIT();

    for (int ch = 0; ch < nch; ch++) {
        if (ch + 1 < nch) {
            wmma_prefetch(sb + ((ch + 1) & 1) * STAGE_SZ, A, B,
                          m0, M, K, (ch + 1) << 5, tid);
            CP_COMMIT();
            CP_WAIT1();
        } else {
            CP_WAIT0();
        }
        __syncthreads();
        const uint32_t st = sb + (ch & 1) * STAGE_SZ;
        WMMA_MAINLOOP_BODY(st)
        __syncthreads();
    }
    WMMA_EPILOGUE()
}

// ---- k_wmmaX: A f32 with 3-stage staging (prefetch distance 2) ----
// Layout: AS[3] f32 staging (18432 each), then {A fp16, B fp16} x2 (20480 each).
#define XST   144
#define XAS(i)   ((i) * 18432)
#define XAFB(j)  (55296 + (j) * STAGE_SZ)
#define XSMEM (55296 + 2 * STAGE_SZ)    // 96256

__global__ void __launch_bounds__(256, 2) k_wmmaX(
    const float* __restrict__ Af, const __half* __restrict__ B,
    const float* __restrict__ bias, int dorelu,
    __half* __restrict__ Chf, int M, int K)
{
    extern __shared__ char smem[];
    const uint32_t sb = s2u(smem);
    const int tid  = threadIdx.x;
    const int lane = tid & 31, w = tid >> 5;
    const int wm0 = (w >> 1) * 32, wn0 = (w & 1) * 64;
    const int m0  = blockIdx.x * 128;

    float c[2][8][4];
    #pragma unroll
    for (int i = 0; i < 2; i++)
        #pragma unroll
        for (int j = 0; j < 8; j++)
            #pragma unroll
            for (int q = 0; q < 4; q++) c[i][j][q] = 0.f;

    const uint32_t aoffs = (uint32_t)((wm0 + (lane & 15)) * STRIDE_B + (lane >> 4) * 16);
    const uint32_t boffs = (uint32_t)((wn0 + ((lane >> 4) & 1) * 8 + (lane & 7)) * STRIDE_B
                                      + ((lane >> 3) & 1) * 16);

    const int nch = K >> 5;

    // A f32 staging prefetch (4 x 16B per thread)
    #define PFA(stage, k0)                                                        \
    {                                                                             \
        _Pragma("unroll")                                                         \
        for (int q = 0; q < 4; q++) {                                             \
            int idx = tid + q * 256;                                              \
            int row = idx >> 3, cg = idx & 7;                                     \
            int gr = m0 + row; if (gr >= M) gr = M - 1;                           \
            size_t aoff = (size_t)gr * K + (k0) + cg * 4;                         \
            cpa16(sb + XAS(stage) + row * XST + cg * 16, Af + aoff);              \
        }                                                                         \
    }
    // B fp16 prefetch (2 x 16B per thread)
    #define PFB(buf, k0)                                                          \
    {                                                                             \
        _Pragma("unroll")                                                         \
        for (int p = 0; p < 2; p++) {                                             \
            int idx = tid + p * 256;                                              \
            int row = idx >> 2, cg = idx & 3;                                     \
            size_t boff = (size_t)row * K + (k0) + cg * 8;                        \
            cpa16(sb + XAFB(buf) + ARR_SZ + row * STRIDE_B + cg * 16, B + boff);  \
        }                                                                         \
    }
    // convert staging f32 -> A fp16
    #define CVTX(stage, buf)                                                      \
    {                                                                             \
        _Pragma("unroll")                                                         \
        for (int q = 0; q < 4; q++) {                                             \
            int idx = tid + q * 256;                                              \
            int row = idx >> 3, cg = idx & 7;                                     \
            uint32_t sa = sb + XAS(stage) + row * XST + cg * 16;                  \
            float vx, vy, vz, vw;                                                 \
            asm volatile("ld.shared.v4.f32 {%0,%1,%2,%3}, [%4];"                  \
                : "=f"(vx), "=f"(vy), "=f"(vz), "=f"(vw) : "r"(sa));              \
            __half2 h0 = __floats2half2_rn(vx, vy);                               \
            __half2 h1 = __floats2half2_rn(vz, vw);                               \
            asm volatile("st.shared.v2.b32 [%0], {%1,%2};"                        \
                :: "r"(sb + XAFB(buf) + row * STRIDE_B + cg * 8),                 \
                   "r"(*(uint32_t*)&h0), "r"(*(uint32_t*)&h1) : "memory");        \
        }                                                                         \
    }

    // prologue: FIFO = GA0, GB0, GA1
    PFA(0, 0)
    CP_COMMIT();
    PFB(0, 0)
    CP_COMMIT();
    if (1 < nch) PFA(1, 1 << 5)
    CP_COMMIT();

    for (int ch = 0; ch < nch; ch++) {
        // commit GB(ch+1) then GA(ch+2); empty groups when out of range
        if (ch + 1 < nch) PFB((ch + 1) & 1, (ch + 1) << 5)
        CP_COMMIT();
        if (ch + 2 < nch) PFA((ch + 2) % 3, (ch + 2) << 5)
        CP_COMMIT();
        CP_WAIT3();                   // GA(ch), GB(ch) complete
        __syncthreads();
        CVTX(ch % 3, ch & 1)
        __syncthreads();
        {
            const uint32_t st = sb + XAFB(ch & 1);
            WMMA_MAINLOOP_BODY(st)
        }
        __syncthreads();
    }
    WMMA_EPILOGUE()
    #undef PFA
    #undef PFB
    #undef CVTX
}

// ======== batched gather agg: good+bad halves, fp16 in/out ========
__global__ void k_agg2(const __half* __restrict__ h, size_t hShiftB,
                       const int* __restrict__ ssrcA, const int* __restrict__ ssrcB,
                       const int* __restrict__ selfB,
                       const int* __restrict__ off, const float* __restrict__ sw,
                       const float* __restrict__ invd, const float* __restrict__ bias,
                       __half* __restrict__ outh, int dorelu)
{
    int wrp = (blockIdx.x * blockDim.x + threadIdx.x) >> 5;
    int lane = threadIdx.x & 31;
    if (wrp >= 2 * NN) return;
    int part = (wrp >= NN);
    int node = wrp - part * NN;
    const int* ssrc = part ? ssrcB : ssrcA;
    const __half* hb = h + (part ? hShiftB : 0);

    int s = off[node], e = off[node + 1];
    float4 acc = make_float4(0.f, 0.f, 0.f, 0.f);
    for (int i = s; i < e; i++) {
        int   src = ssrc[i];
        float w   = sw[i];
        uint2 raw = *(const uint2*)(hb + (size_t)src * FD + lane * 4);
        float2 f0 = __half22float2(*(__half2*)&raw.x);
        float2 f1 = __half22float2(*(__half2*)&raw.y);
        acc.x = fmaf(w, f0.x, acc.x);
        acc.y = fmaf(w, f0.y, acc.y);
        acc.z = fmaf(w, f1.x, acc.z);
        acc.w = fmaf(w, f1.y, acc.w);
    }
    int self = part ? (selfB ? selfB[node] : node) : node;
    float id = invd[node];
    uint2 rs = *(const uint2*)(hb + (size_t)self * FD + lane * 4);
    float2 s0 = __half22float2(*(__half2*)&rs.x);
    float2 s1 = __half22float2(*(__half2*)&rs.y);
    float4 b = *(const float4*)(bias + lane * 4);
    acc.x = fmaf(id, s0.x, acc.x) + b.x;
    acc.y = fmaf(id, s0.y, acc.y) + b.y;
    acc.z = fmaf(id, s1.x, acc.z) + b.z;
    acc.w = fmaf(id, s1.y, acc.w) + b.w;
    if (dorelu) {
        acc.x = fmaxf(acc.x, 0.f); acc.y = fmaxf(acc.y, 0.f);
        acc.z = fmaxf(acc.z, 0.f); acc.w = fmaxf(acc.w, 0.f);
    }
    __half2 o0 = __floats2half2_rn(acc.x, acc.y);
    __half2 o1 = __floats2half2_rn(acc.z, acc.w);
    *(uint2*)(outh + (size_t)wrp * FD + lane * 4) =
        make_uint2(*(uint32_t*)&o0, *(uint32_t*)&o1);
}

// ===== batched fused hop-agg + bilinear score: cols 10 (good), 11 (bad) =====
__global__ void k_aggscore2(const __half* __restrict__ G, size_t hShiftB,
                            const __half* __restrict__ T,
                            const int* __restrict__ off, const int* __restrict__ ssrc,
                            const float* __restrict__ sw, const float* __restrict__ invd,
                            const float* __restrict__ b3, float* __restrict__ out)
{
    const unsigned FULL = 0xffffffffu;
    int wrp = (blockIdx.x * blockDim.x + threadIdx.x) >> 5;
    int lane = threadIdx.x & 31;
    if (wrp >= 2 * NN) return;
    int part = (wrp >= NN);
    int node = wrp - part * NN;
    const __half* Gb = G + (part ? hShiftB : 0);

    uint2 tr = *(const uint2*)(T + (size_t)node * FD + lane * 4);
    float2 t0 = __half22float2(*(__half2*)&tr.x);
    float2 t1 = __half22float2(*(__half2*)&tr.y);
    int s = off[node], e = off[node + 1];
    float acc = 0.f;
    for (int i = s; i < e; i++) {
        int   src = ssrc[i];
        float w   = sw[i];
        uint2 raw = *(const uint2*)(Gb + (size_t)src * FD + lane * 4);
        float2 f0 = __half22float2(*(__half2*)&raw.x);
        float2 f1 = __half22float2(*(__half2*)&raw.y);
        acc = fmaf(w, t0.x * f0.x + t0.y * f0.y + t1.x * f1.x + t1.y * f1.y, acc);
    }
    uint2 rs = *(const uint2*)(Gb + (size_t)node * FD + lane * 4);
    float2 s0 = __half22float2(*(__half2*)&rs.x);
    float2 s1 = __half22float2(*(__half2*)&rs.y);
    float4 bb = *(const float4*)(b3 + lane * 4);
    acc = fmaf(invd[node], t0.x * s0.x + t0.y * s0.y + t1.x * s1.x + t1.y * s1.y, acc);
    acc += t0.x * bb.x + t0.y * bb.y + t1.x * bb.z + t1.y * bb.w;
    #pragma unroll
    for (int d = 16; d > 0; d >>= 1) acc += __shfl_xor_sync(FULL, acc, d);
    if (lane == 0)
        out[(size_t)node * OUTC + 10 + part] = 1.0f / (1.0f + expf(-acc));
}

// ================= classifier =================
__global__ void k_gemm10(const __half* __restrict__ A, const float* __restrict__ W,
                         float* __restrict__ C)
{
    __shared__ float w[FD * NC];
    for (int i = threadIdx.x; i < FD * NC; i += blockDim.x) w[i] = W[i];
    __syncthreads();
    int r = blockIdx.x * blockDim.x + threadIdx.x;
    if (r >= NN) return;
    float acc[NC];
    #pragma unroll
    for (int j = 0; j < NC; j++) acc[j] = 0.f;
    const uint4* ap = (const uint4*)(A + (size_t)r * FD);
    #pragma unroll 4
    for (int k8 = 0; k8 < 16; k8++) {
        uint4 u = ap[k8];
        const __half2* hp = (const __half2*)&u;
        float2 f0 = __half22float2(hp[0]);
        float2 f1 = __half22float2(hp[1]);
        float2 f2 = __half22float2(hp[2]);
        float2 f3 = __half22float2(hp[3]);
        int k = k8 * 8;
        #pragma unroll
        for (int j = 0; j < NC; j++) {
            acc[j] = fmaf(f0.x, w[(k + 0) * NC + j], acc[j]);
            acc[j] = fmaf(f0.y, w[(k + 1) * NC + j], acc[j]);
            acc[j] = fmaf(f1.x, w[(k + 2) * NC + j], acc[j]);
            acc[j] = fmaf(f1.y, w[(k + 3) * NC + j], acc[j]);
            acc[j] = fmaf(f2.x, w[(k + 4) * NC + j], acc[j]);
            acc[j] = fmaf(f2.y, w[(k + 5) * NC + j], acc[j]);
            acc[j] = fmaf(f3.x, w[(k + 6) * NC + j], acc[j]);
            acc[j] = fmaf(f3.y, w[(k + 7) * NC + j], acc[j]);
        }
    }
    #pragma unroll
    for (int j = 0; j < NC; j++) C[(size_t)r * NC + j] = acc[j];
}

__global__ void k_agg10(const float* __restrict__ h, const int* __restrict__ off,
                        const int* __restrict__ ssrc, const float* __restrict__ sw,
                        const float* __restrict__ invd, const float* __restrict__ bc,
                        float* __restrict__ out)
{
    int node = (blockIdx.x * blockDim.x + threadIdx.x) >> 5;
    int lane = threadIdx.x & 31;
    if (node >= NN || lane >= NC) return;
    int s = off[node], e = off[node + 1];
    float acc = 0.f;
    for (int i = s; i < e; i++) {
        int src = ssrc[i];
        acc = fmaf(sw[i], h[(size_t)src * NC + lane], acc);
    }
    acc = fmaf(invd[node], h[(size_t)node * NC + lane], acc) + bc[lane];
    out[(size_t)node * OUTC + lane] = acc;
}

// ================= host =================
extern "C" void kernel_launch(void* const* d_in, const int* in_sizes, int n_in,
                              void* d_out, int out_size)
{
    const float* x    = (const float*)d_in[0];
    const int*   ei   = (const int*)  d_in[1];
    const int*   eh   = (const int*)  d_in[2];
    const int*   perm = (const int*)  d_in[4];
    const float* W1   = (const float*)d_in[5];
    const float* b1   = (const float*)d_in[6];
    const float* W2   = (const float*)d_in[7];
    const float* b2   = (const float*)d_in[8];
    const float* W3   = (const float*)d_in[9];
    const float* b3   = (const float*)d_in[10];
    const float* M1   = (const float*)d_in[11];
    const float* mb1  = (const float*)d_in[12];
    const float* M2   = (const float*)d_in[13];
    const float* mb2  = (const float*)d_in[14];
    const float* Wc   = (const float*)d_in[15];
    const float* bc   = (const float*)d_in[16];
    const float* Wd   = (const float*)d_in[17];
    float* out = (float*)d_out;

    float *C10, *dis, *invd, *sw;
    __half *Hh, *P1, *Gh, *P2, *P3, *P4, *Th, *Wf;
    int *cnt, *off, *cur, *btot, *ssrc, *ssrcp;
    cudaGetSymbolAddress((void**)&Hh,   g_Hh);
    cudaGetSymbolAddress((void**)&P1,   g_P1);
    cudaGetSymbolAddress((void**)&Gh,   g_Gh);
    cudaGetSymbolAddress((void**)&P2,   g_P2);
    cudaGetSymbolAddress((void**)&P3,   g_P3);
    cudaGetSymbolAddress((void**)&P4,   g_P4);
    cudaGetSymbolAddress((void**)&Th,   g_Th);
    cudaGetSymbolAddress((void**)&C10,  g_C10);
    cudaGetSymbolAddress((void**)&Wf,   g_Wf);
    cudaGetSymbolAddress((void**)&cnt,  g_cnt);
    cudaGetSymbolAddress((void**)&dis,  g_dis);
    cudaGetSymbolAddress((void**)&invd, g_invd);
    cudaGetSymbolAddress((void**)&off,  g_off);
    cudaGetSymbolAddress((void**)&cur,  g_cur);
    cudaGetSymbolAddress((void**)&btot, g_btot);
    cudaGetSymbolAddress((void**)&ssrc, g_ssrc);
    cudaGetSymbolAddress((void**)&ssrcp,g_ssrcp);
    cudaGetSymbolAddress((void**)&sw,   g_sw);

    cudaFuncSetAttribute(k_wmma,  cudaFuncAttributeMaxDynamicSharedMemorySize, SMEM_SZ);
    cudaFuncSetAttribute(k_wmmaX, cudaFuncAttributeMaxDynamicSharedMemorySize, XSMEM);

    const int TE  = 256;
    const int GN  = (NN + TE - 1) / TE;
    const int GE2 = (2 * NE + TE - 1) / TE;
    const int GW  = (NN * 32 + TE - 1) / TE;
    const int GW2 = (2 * NN * 32 + TE - 1) / TE;
    const int GM  = (NN + 127) / 128;
    const int GM2 = (2 * NN + 127) / 128;
    const size_t HB = (size_t)NN * FD;

    // ---- prologue (node 5 = k_wmmaX for ncu) ----
    cudaMemsetAsync(cnt, 0, sizeof(int) * 2 * NN);
    k_count2<<<GE2, TE>>>(ei + NE, eh + NE, cnt);
    k_prepw<<<(512 * 128 + 255) / 256, 256>>>(W1, Wf + WOFF_W1, 512);
    k_deg2<<<(2 * NN + TE - 1) / TE, TE>>>(cnt, dis, invd);
    k_wmmaX<<<GM, 256, XSMEM>>>(x, Wf + WOFF_W1, nullptr, 0, Hh, NN, 512);

    // ---- scans + placement ----
    k_scan_blk2<<<2 * NB, SCB>>>(cnt, off, btot);
    k_scan_tot2<<<2, 128>>>(btot, off);
    k_scan_add2<<<2 * GN, TE>>>(off, btot, cur, GN);
    k_place2<<<GE2, TE>>>(ei, eh, dis, cur, ssrc, sw, perm, ssrcp);
    k_prepw5<<<(5 * 128 * 128 + 255) / 256, 256>>>(W2, W3, M1, M2, Wd, Wf);

    // ---- layer1 batched agg (Hh for both halves) -> P1[2NN] ----
    k_agg2<<<GW2, TE>>>(Hh, 0, ssrc, ssrcp, perm, off, sw, invd, b1, P1, 1);

    // ---- batched W2 GEMM -> Gh[2NN] ----
    k_wmma<<<GM2, 256, SMEM_SZ>>>(P1, Wf + WOFF_W2, nullptr, 0, Gh, 2 * NN, 128);

    // ---- layer2 batched agg (Gh halves) -> P2[2NN] ----
    k_agg2<<<GW2, TE>>>(Gh, HB, ssrc, ssrc, nullptr, off, sw, invd, b2, P2, 1);

    // ---- MLP / discriminator / classifier (good P2) ----
    k_wmma<<<GM, 256, SMEM_SZ>>>(P2, Wf + WOFF_M1, mb1, 1, P3, NN, 128);
    k_gemm10<<<GN, TE>>>(P2, Wc, C10);
    k_agg10<<<GW, TE>>>(C10, off, ssrc, sw, invd, bc, out);
    k_wmma<<<GM, 256, SMEM_SZ>>>(P3, Wf + WOFF_M2, mb2, 0, P4, NN, 128);
    k_wmma<<<GM, 256, SMEM_SZ>>>(P4, Wf + WOFF_WD, nullptr, 0, Th, NN, 128);

    // ---- batched W3 GEMM (P2 -> P1 reuse) + batched score ----
    k_wmma<<<GM2, 256, SMEM_SZ>>>(P2, Wf + WOFF_W3, nullptr, 0, P1, 2 * NN, 128);
    k_aggscore2<<<GW2, TE>>>(P1, HB, Th, off + (NN + 1), ssrc + NE, sw + NE,
                             invd + NN, b3, out);
}

// round 17
// speedup vs baseline: 1.0334x; 1.0334x over previous
#include <cuda_runtime.h>
#include <cuda_fp16.h>
#include <math.h>
#include <stdint.h>

#define NN 100000
#define NE 1600000
#define NF 512
#define FD 128
#define NC 10
#define OUTC 12

// ================= PTX helpers (sm_80-compatible only) =================
__device__ __forceinline__ uint32_t s2u(const void* p) {
    uint32_t a;
    asm("{ .reg .u64 t; cvta.to.shared.u64 t, %1; cvt.u32.u64 %0, t; }"
        : "=r"(a) : "l"(p));
    return a;
}
__device__ __forceinline__ void cpa16(uint32_t dst, const void* src) {
    asm volatile("cp.async.cg.shared.global [%0], [%1], 16;" :: "r"(dst), "l"(src));
}
#define CP_COMMIT() asm volatile("cp.async.commit_group;" ::: "memory")
#define CP_WAIT1()  asm volatile("cp.async.wait_group 1;" ::: "memory")
#define CP_WAIT3()  asm volatile("cp.async.wait_group 3;" ::: "memory")
#define CP_WAIT0()  asm volatile("cp.async.wait_group 0;" ::: "memory")

__device__ __forceinline__ void ldsm4(uint32_t* r, uint32_t addr) {
    asm volatile("ldmatrix.sync.aligned.m8n8.x4.shared.b16 {%0,%1,%2,%3}, [%4];"
                 : "=r"(r[0]), "=r"(r[1]), "=r"(r[2]), "=r"(r[3]) : "r"(addr));
}
__device__ __forceinline__ void mma16816h(float* c, const uint32_t* a, const uint32_t* b) {
    asm volatile("mma.sync.aligned.m16n8k16.row.col.f32.f16.f16.f32 "
                 "{%0,%1,%2,%3}, {%4,%5,%6,%7}, {%8,%9}, {%0,%1,%2,%3};"
                 : "+f"(c[0]), "+f"(c[1]), "+f"(c[2]), "+f"(c[3])
                 : "r"(a[0]), "r"(a[1]), "r"(a[2]), "r"(a[3]), "r"(b[0]), "r"(b[1]));
}

// ================= scratch (device globals) =================
__device__ __half g_Hh [(size_t)NN * FD];
__device__ __half g_P1 [(size_t)2 * NN * FD];   // layer1 agg out; later W3 GEMM out
__device__ __half g_Gh [(size_t)2 * NN * FD];
__device__ __half g_P2 [(size_t)2 * NN * FD];
__device__ __half g_Th [(size_t)NN * FD];
__device__ float g_C10[(size_t)NN * NC];
#define WOFF_W1 0
#define WOFF_W2 (128 * 512)
#define WOFF_W3 (WOFF_W2 + 128 * 128)
#define WOFF_M1 (WOFF_W3 + 128 * 128)
#define WOFF_M2 (WOFF_M1 + 128 * 128)
#define WOFF_WD (WOFF_M2 + 128 * 128)
#define WTOT    (WOFF_WD + 128 * 128)
__device__ __half g_Wf[WTOT];
__device__ int   g_cnt [2 * NN];
__device__ float g_dis [2 * NN];
__device__ float g_invd[2 * NN];
__device__ int   g_off [2 * (NN + 1)];
__device__ int   g_cur [2 * NN];
__device__ int   g_btot[2 * 128];
__device__ int   g_ssrc[2 * NE];
__device__ int   g_ssrcp[NE];
__device__ float g_sw  [2 * NE];

// ================= CSR build (merged kernels) =================
__global__ void k_count2(const int* __restrict__ d0, const int* __restrict__ d1,
                         int* __restrict__ cnt) {
    int i = blockIdx.x * blockDim.x + threadIdx.x;
    if (i < NE) atomicAdd(&cnt[d0[i]], 1);
    else {
        int j = i - NE;
        if (j < NE) atomicAdd(&cnt[NN + d1[j]], 1);
    }
}

__global__ void k_deg2(const int* __restrict__ cnt, float* __restrict__ dis,
                       float* __restrict__ invd) {
    int i = blockIdx.x * blockDim.x + threadIdx.x;
    if (i < 2 * NN) {
        float d = (float)(cnt[i] + 1);
        dis[i]  = rsqrtf(d);
        invd[i] = 1.0f / d;
    }
}

#define SCB 1024
#define NB  ((NN + SCB - 1) / SCB)
__global__ void k_scan_blk2(const int* __restrict__ cnt, int* __restrict__ off,
                            int* __restrict__ btot) {
    __shared__ int ws[32];
    const unsigned FULL = 0xffffffffu;
    int g = blockIdx.x / NB, b = blockIdx.x % NB;
    const int* c = cnt + g * NN;
    int* o  = off + g * (NN + 1);
    int* bt = btot + g * 128;
    int t = threadIdx.x, w = t >> 5, l = t & 31;
    int i = b * SCB + t;
    int v = (i < NN) ? c[i] : 0;
    int s = v;
    #pragma unroll
    for (int d = 1; d < 32; d <<= 1) {
        int oo = __shfl_up_sync(FULL, s, d);
        if (l >= d) s += oo;
    }
    if (l == 31) ws[w] = s;
    __syncthreads();
    if (w == 0) {
        int x2 = ws[l];
        #pragma unroll
        for (int d = 1; d < 32; d <<= 1) {
            int oo = __shfl_up_sync(FULL, x2, d);
            if (l >= d) x2 += oo;
        }
        ws[l] = x2;
    }
    __syncthreads();
    int incl = s + (w > 0 ? ws[w - 1] : 0);
    if (i < NN) o[i] = incl - v;
    if (t == SCB - 1) bt[b] = incl;
}

__global__ void k_scan_tot2(int* __restrict__ btot, int* __restrict__ off) {
    __shared__ int sh[128];
    int g = blockIdx.x;
    int* bt = btot + g * 128;
    int t = threadIdx.x;
    int v = (t < NB) ? bt[t] : 0;
    sh[t] = v;
    __syncthreads();
    #pragma unroll
    for (int d = 1; d < 128; d <<= 1) {
        int o = (t >= d) ? sh[t - d] : 0;
        __syncthreads();
        sh[t] += o;
        __syncthreads();
    }
    if (t < NB) bt[t] = sh[t] - v;
    if (t == 127) off[g * (NN + 1) + NN] = sh[127];
}

__global__ void k_scan_add2(int* __restrict__ off, const int* __restrict__ btot,
                            int* __restrict__ cur, int gpb) {
    int g = blockIdx.x / gpb;
    int i = (blockIdx.x % gpb) * blockDim.x + threadIdx.x;
    if (i < NN) {
        int e = off[g * (NN + 1) + i] + btot[g * 128 + (i >> 10)];
        off[g * (NN + 1) + i] = e;
        cur[g * NN + i] = e;
    }
}

__global__ void k_place2(const int* __restrict__ ei, const int* __restrict__ eh,
                         const float* __restrict__ dis, int* __restrict__ cur,
                         int* __restrict__ ssrc, float* __restrict__ sw,
                         const int* __restrict__ perm, int* __restrict__ ssrcp) {
    int gi = blockIdx.x * blockDim.x + threadIdx.x;
    if (gi < NE) {
        int s = ei[gi], d = ei[NE + gi];
        int p = atomicAdd(&cur[d], 1);
        ssrc[p]  = s;
        sw[p]    = dis[s] * dis[d];
        ssrcp[p] = perm[s];
    } else {
        int e = gi - NE;
        if (e < NE) {
            int s = eh[e], d = eh[NE + e];
            int p = atomicAdd(&cur[NN + d], 1);
            ssrc[NE + p] = s;
            sw[NE + p]   = dis[NN + s] * dis[NN + d];
        }
    }
}

// ================= weight prep =================
__global__ void k_prepw(const float* __restrict__ W, __half* __restrict__ Bt, int K) {
    int i = blockIdx.x * blockDim.x + threadIdx.x;
    if (i < K * 128) {
        int n = i / K, k = i - n * K;
        Bt[(size_t)n * K + k] = __float2half(W[(size_t)k * 128 + n]);
    }
}

__global__ void k_prepw5(const float* __restrict__ W2, const float* __restrict__ W3,
                         const float* __restrict__ M1, const float* __restrict__ M2,
                         const float* __restrict__ Wd, __half* __restrict__ Wf) {
    int i = blockIdx.x * blockDim.x + threadIdx.x;
    if (i >= 5 * 128 * 128) return;
    int r = i >> 14, j = i & 16383;
    const float* W = (r == 0) ? W2 : (r == 1) ? W3 : (r == 2) ? M1 : (r == 3) ? M2 : Wd;
    int woff = (r == 0) ? WOFF_W2 : (r == 1) ? WOFF_W3 : (r == 2) ? WOFF_M1
             : (r == 3) ? WOFF_M2 : WOFF_WD;
    int n = j >> 7, k = j & 127;
    Wf[woff + (size_t)n * 128 + k] = __float2half(W[(size_t)k * 128 + n]);
}

// ================= fp16 mma.sync GEMM =================
#define STRIDE_B 80
#define ARR_SZ   (128 * STRIDE_B)       // 10240
#define STAGE_SZ (2 * ARR_SZ)           // 20480 (A + B)
#define SMEM_SZ  (2 * STAGE_SZ)         // 40960

__device__ __forceinline__ void wmma_prefetch(
    uint32_t sbase, const __half* A, const __half* B,
    int m0, int M, int K, int k0, int tid)
{
    #pragma unroll
    for (int p = 0; p < 2; p++) {
        int idx = tid + p * 256;
        int row = idx >> 2, cg = idx & 3;
        int gr = m0 + row; if (gr >= M) gr = M - 1;
        size_t aoff = (size_t)gr * K + k0 + cg * 8;
        size_t boff = (size_t)row * K + k0 + cg * 8;
        uint32_t so = row * STRIDE_B + cg * 16;
        cpa16(sbase + 0 * ARR_SZ + so, A + aoff);
        cpa16(sbase + 1 * ARR_SZ + so, B + boff);
    }
}

// mainloop over one 32-col chunk; A at base aB, B at base bB
#define WMMA_CHUNK(aB, bB)                                                       \
    {                                                                            \
        _Pragma("unroll")                                                        \
        for (int kk = 0; kk < 2; kk++) {                                         \
            const uint32_t kb = kk * 32;                                         \
            uint32_t ah[2][4], bh[4][4];                                         \
            _Pragma("unroll")                                                    \
            for (int mt = 0; mt < 2; mt++)                                       \
                ldsm4(ah[mt], (aB) + aoffs + mt * (16 * STRIDE_B) + kb);         \
            _Pragma("unroll")                                                    \
            for (int np = 0; np < 4; np++)                                       \
                ldsm4(bh[np], (bB) + boffs + np * (16 * STRIDE_B) + kb);         \
            _Pragma("unroll")                                                    \
            for (int mt = 0; mt < 2; mt++)                                       \
                _Pragma("unroll")                                                \
                for (int nt = 0; nt < 8; nt++)                                   \
                    mma16816h(c[mt][nt], ah[mt], &bh[nt >> 1][(nt & 1) * 2]);    \
        }                                                                        \
    }

#define WMMA_EPILOGUE()                                                          \
    _Pragma("unroll")                                                            \
    for (int mt = 0; mt < 2; mt++) {                                             \
        _Pragma("unroll")                                                        \
        for (int part = 0; part < 2; part++) {                                   \
            int gr = m0 + wm0 + mt * 16 + (lane >> 2) + part * 8;                \
            if (gr >= M) continue;                                               \
            _Pragma("unroll")                                                    \
            for (int nt = 0; nt < 8; nt++) {                                     \
                int gcol = wn0 + nt * 8 + (lane & 3) * 2;                        \
                float v0 = c[mt][nt][part * 2 + 0];                              \
                float v1 = c[mt][nt][part * 2 + 1];                              \
                if (bias) { v0 += bias[gcol]; v1 += bias[gcol + 1]; }            \
                if (dorelu) { v0 = fmaxf(v0, 0.f); v1 = fmaxf(v1, 0.f); }        \
                __half2 hh = __floats2half2_rn(v0, v1);                          \
                *(uint32_t*)(Chf + (size_t)gr * FD + gcol) = *(uint32_t*)&hh;    \
            }                                                                    \
        }                                                                        \
    }

__global__ void __launch_bounds__(256, 2) k_wmma(
    const __half* __restrict__ A, const __half* __restrict__ B,
    const float* __restrict__ bias, int dorelu,
    __half* __restrict__ Chf, int M, int K)
{
    extern __shared__ char smem[];
    const uint32_t sb = s2u(smem);
    const int tid  = threadIdx.x;
    const int lane = tid & 31, w = tid >> 5;
    const int wm0 = (w >> 1) * 32, wn0 = (w & 1) * 64;
    const int m0  = blockIdx.x * 128;

    float c[2][8][4];
    #pragma unroll
    for (int i = 0; i < 2; i++)
        #pragma unroll
        for (int j = 0; j < 8; j++)
            #pragma unroll
            for (int q = 0; q < 4; q++) c[i][j][q] = 0.f;

    const uint32_t aoffs = (uint32_t)((wm0 + (lane & 15)) * STRIDE_B + (lane >> 4) * 16);
    const uint32_t boffs = (uint32_t)((wn0 + ((lane >> 4) & 1) * 8 + (lane & 7)) * STRIDE_B
                                      + ((lane >> 3) & 1) * 16);

    const int nch = K >> 5;
    wmma_prefetch(sb, A, B, m0, M, K, 0, tid);
    CP_COMMIT();

    for (int ch = 0; ch < nch; ch++) {
        if (ch + 1 < nch) {
            wmma_prefetch(sb + ((ch + 1) & 1) * STAGE_SZ, A, B,
                          m0, M, K, (ch + 1) << 5, tid);
            CP_COMMIT();
            CP_WAIT1();
        } else {
            CP_WAIT0();
        }
        __syncthreads();
        const uint32_t st = sb + (ch & 1) * STAGE_SZ;
        WMMA_CHUNK(st, st + ARR_SZ)
        __syncthreads();
    }
    WMMA_EPILOGUE()
}

// ---- k_wmmaX: A f32 with 3-stage staging (for x @ W1) ----
#define XST   144
#define XAS(i)   ((i) * 18432)
#define XAFB(j)  (55296 + (j) * STAGE_SZ)
#define XSMEM (55296 + 2 * STAGE_SZ)    // 96256

__global__ void __launch_bounds__(256, 2) k_wmmaX(
    const float* __restrict__ Af, const __half* __restrict__ B,
    const float* __restrict__ bias, int dorelu,
    __half* __restrict__ Chf, int M, int K)
{
    extern __shared__ char smem[];
    const uint32_t sb = s2u(smem);
    const int tid  = threadIdx.x;
    const int lane = tid & 31, w = tid >> 5;
    const int wm0 = (w >> 1) * 32, wn0 = (w & 1) * 64;
    const int m0  = blockIdx.x * 128;

    float c[2][8][4];
    #pragma unroll
    for (int i = 0; i < 2; i++)
        #pragma unroll
        for (int j = 0; j < 8; j++)
            #pragma unroll
            for (int q = 0; q < 4; q++) c[i][j][q] = 0.f;

    const uint32_t aoffs = (uint32_t)((wm0 + (lane & 15)) * STRIDE_B + (lane >> 4) * 16);
    const uint32_t boffs = (uint32_t)((wn0 + ((lane >> 4) & 1) * 8 + (lane & 7)) * STRIDE_B
                                      + ((lane >> 3) & 1) * 16);

    const int nch = K >> 5;

    #define PFA(stage, k0)                                                        \
    {                                                                             \
        _Pragma("unroll")                                                         \
        for (int q = 0; q < 4; q++) {                                             \
            int idx = tid + q * 256;                                              \
            int row = idx >> 3, cg = idx & 7;                                     \
            int gr = m0 + row; if (gr >= M) gr = M - 1;                           \
            size_t aoff = (size_t)gr * K + (k0) + cg * 4;                         \
            cpa16(sb + XAS(stage) + row * XST + cg * 16, Af + aoff);              \
        }                                                                         \
    }
    #define PFB(buf, k0)                                                          \
    {                                                                             \
        _Pragma("unroll")                                                         \
        for (int p = 0; p < 2; p++) {                                             \
            int idx = tid + p * 256;                                              \
            int row = idx >> 2, cg = idx & 3;                                     \
            size_t boff = (size_t)row * K + (k0) + cg * 8;                        \
            cpa16(sb + XAFB(buf) + ARR_SZ + row * STRIDE_B + cg * 16, B + boff);  \
        }                                                                         \
    }
    #define CVTX(stage, buf)                                                      \
    {                                                                             \
        _Pragma("unroll")                                                         \
        for (int q = 0; q < 4; q++) {                                             \
            int idx = tid + q * 256;                                              \
            int row = idx >> 3, cg = idx & 7;                                     \
            uint32_t sa = sb + XAS(stage) + row * XST + cg * 16;                  \
            float vx, vy, vz, vw;                                                 \
            asm volatile("ld.shared.v4.f32 {%0,%1,%2,%3}, [%4];"                  \
                : "=f"(vx), "=f"(vy), "=f"(vz), "=f"(vw) : "r"(sa));              \
            __half2 h0 = __floats2half2_rn(vx, vy);                               \
            __half2 h1 = __floats2half2_rn(vz, vw);                               \
            asm volatile("st.shared.v2.b32 [%0], {%1,%2};"                        \
                :: "r"(sb + XAFB(buf) + row * STRIDE_B + cg * 8),                 \
                   "r"(*(uint32_t*)&h0), "r"(*(uint32_t*)&h1) : "memory");        \
        }                                                                         \
    }

    PFA(0, 0)
    CP_COMMIT();
    PFB(0, 0)
    CP_COMMIT();
    if (1 < nch) PFA(1, 1 << 5)
    CP_COMMIT();

    for (int ch = 0; ch < nch; ch++) {
        if (ch + 1 < nch) PFB((ch + 1) & 1, (ch + 1) << 5)
        CP_COMMIT();
        if (ch + 2 < nch) PFA((ch + 2) % 3, (ch + 2) << 5)
        CP_COMMIT();
        CP_WAIT3();
        __syncthreads();
        CVTX(ch % 3, ch & 1)
        __syncthreads();
        {
            const uint32_t st = sb + XAFB(ch & 1);
            WMMA_CHUNK(st, st + ARR_SZ)
        }
        __syncthreads();
    }
    WMMA_EPILOGUE()
    #undef PFA
    #undef PFB
    #undef CVTX
}

// ---- k_wmma3: fused P2 @ M1 (relu) @ M2 @ Wd -> Th, intermediates in smem ----
// smem: A tile 4 chunks (40960) + W tile 4 chunks (40960) = 81920.
#define W3_A(c)  ((c) * ARR_SZ)
#define W3_W(c)  (40960 + (c) * ARR_SZ)
#define W3_SMEM  81920

__global__ void __launch_bounds__(256, 2) k_wmma3(
    const __half* __restrict__ A, const __half* __restrict__ Wm1,
    const __half* __restrict__ Wm2, const __half* __restrict__ Wwd,
    const float* __restrict__ mb1, const float* __restrict__ mb2,
    __half* __restrict__ Chf, int M)
{
    extern __shared__ char smem[];
    const uint32_t sb = s2u(smem);
    const int tid  = threadIdx.x;
    const int lane = tid & 31, w = tid >> 5;
    const int wm0 = (w >> 1) * 32, wn0 = (w & 1) * 64;
    const int m0  = blockIdx.x * 128;

    const uint32_t aoffs = (uint32_t)((wm0 + (lane & 15)) * STRIDE_B + (lane >> 4) * 16);
    const uint32_t boffs = (uint32_t)((wn0 + ((lane >> 4) & 1) * 8 + (lane & 7)) * STRIDE_B
                                      + ((lane >> 3) & 1) * 16);

    // load full A (P2 tile) and W (M1), K=128 -> 4 chunks, 8 cp/thread each
    #pragma unroll
    for (int p = 0; p < 8; p++) {
        int idx = tid + p * 256;
        int ch  = idx >> 9;            // 0..3
        int r   = (idx >> 2) & 127;
        int cg  = idx & 3;
        int gr = m0 + r; if (gr >= M) gr = M - 1;
        cpa16(sb + W3_A(ch) + r * STRIDE_B + cg * 16,
              A + (size_t)gr * FD + ch * 32 + cg * 8);
        cpa16(sb + W3_W(ch) + r * STRIDE_B + cg * 16,
              Wm1 + (size_t)r * FD + ch * 32 + cg * 8);
    }
    CP_COMMIT();
    CP_WAIT0();
    __syncthreads();

    float c[2][8][4];
    #pragma unroll
    for (int g = 0; g < 3; g++) {
        #pragma unroll
        for (int i = 0; i < 2; i++)
            #pragma unroll
            for (int j = 0; j < 8; j++)
                #pragma unroll
                for (int q = 0; q < 4; q++) c[i][j][q] = 0.f;

        #pragma unroll
        for (int ch = 0; ch < 4; ch++)
            WMMA_CHUNK(sb + W3_A(ch), sb + W3_W(ch))
        __syncthreads();   // all warps done reading A and W

        // prefetch next weight into W buffer (overlaps epilogue)
        if (g < 2) {
            const __half* Wn = (g == 0) ? Wm2 : Wwd;
            #pragma unroll
            for (int p = 0; p < 8; p++) {
                int idx = tid + p * 256;
                int ch  = idx >> 9;
                int r   = (idx >> 2) & 127;
                int cg  = idx & 3;
                cpa16(sb + W3_W(ch) + r * STRIDE_B + cg * 16,
                      Wn + (size_t)r * FD + ch * 32 + cg * 8);
            }
            CP_COMMIT();
        }

        if (g < 2) {
            // epilogue -> A smem (bias for g=0 is mb1 + relu; g=1 mb2, no relu)
            const float* bias = (g == 0) ? mb1 : mb2;
            #pragma unroll
            for (int mt = 0; mt < 2; mt++) {
                #pragma unroll
                for (int part = 0; part < 2; part++) {
                    int lr = wm0 + mt * 16 + (lane >> 2) + part * 8;
                    #pragma unroll
                    for (int nt = 0; nt < 8; nt++) {
                        int gcol = wn0 + nt * 8 + (lane & 3) * 2;
                        float v0 = c[mt][nt][part * 2 + 0] + bias[gcol];
                        float v1 = c[mt][nt][part * 2 + 1] + bias[gcol + 1];
                        if (g == 0) { v0 = fmaxf(v0, 0.f); v1 = fmaxf(v1, 0.f); }
                        __half2 hh = __floats2half2_rn(v0, v1);
                        asm volatile("st.shared.b32 [%0], %1;"
                            :: "r"(sb + W3_A(gcol >> 5) + lr * STRIDE_B
                                   + (gcol & 31) * 2),
                               "r"(*(uint32_t*)&hh) : "memory");
                    }
                }
            }
            CP_WAIT0();
            __syncthreads();   // new A + new W visible to all
        } else {
            // final epilogue -> global Th
            #pragma unroll
            for (int mt = 0; mt < 2; mt++) {
                #pragma unroll
                for (int part = 0; part < 2; part++) {
                    int gr = m0 + wm0 + mt * 16 + (lane >> 2) + part * 8;
                    if (gr >= M) continue;
                    #pragma unroll
                    for (int nt = 0; nt < 8; nt++) {
                        int gcol = wn0 + nt * 8 + (lane & 3) * 2;
                        __half2 hh = __floats2half2_rn(c[mt][nt][part * 2 + 0],
                                                       c[mt][nt][part * 2 + 1]);
                        *(uint32_t*)(Chf + (size_t)gr * FD + gcol) = *(uint32_t*)&hh;
                    }
                }
            }
        }
    }
}

// ======== batched gather agg: good+bad halves, fp16 in/out ========
__global__ void k_agg2(const __half* __restrict__ h, size_t hShiftB,
                       const int* __restrict__ ssrcA, const int* __restrict__ ssrcB,
                       const int* __restrict__ selfB,
                       const int* __restrict__ off, const float* __restrict__ sw,
                       const float* __restrict__ invd, const float* __restrict__ bias,
                       __half* __restrict__ outh, int dorelu)
{
    int wrp = (blockIdx.x * blockDim.x + threadIdx.x) >> 5;
    int lane = threadIdx.x & 31;
    if (wrp >= 2 * NN) return;
    int part = (wrp >= NN);
    int node = wrp - part * NN;
    const int* ssrc = part ? ssrcB : ssrcA;
    const __half* hb = h + (part ? hShiftB : 0);

    int s = off[node], e = off[node + 1];
    float4 acc = make_float4(0.f, 0.f, 0.f, 0.f);
    for (int i = s; i < e; i++) {
        int   src = ssrc[i];
        float w   = sw[i];
        uint2 raw = *(const uint2*)(hb + (size_t)src * FD + lane * 4);
        float2 f0 = __half22float2(*(__half2*)&raw.x);
        float2 f1 = __half22float2(*(__half2*)&raw.y);
        acc.x = fmaf(w, f0.x, acc.x);
        acc.y = fmaf(w, f0.y, acc.y);
        acc.z = fmaf(w, f1.x, acc.z);
        acc.w = fmaf(w, f1.y, acc.w);
    }
    int self = part ? (selfB ? selfB[node] : node) : node;
    float id = invd[node];
    uint2 rs = *(const uint2*)(hb + (size_t)self * FD + lane * 4);
    float2 s0 = __half22float2(*(__half2*)&rs.x);
    float2 s1 = __half22float2(*(__half2*)&rs.y);
    float4 b = *(const float4*)(bias + lane * 4);
    acc.x = fmaf(id, s0.x, acc.x) + b.x;
    acc.y = fmaf(id, s0.y, acc.y) + b.y;
    acc.z = fmaf(id, s1.x, acc.z) + b.z;
    acc.w = fmaf(id, s1.y, acc.w) + b.w;
    if (dorelu) {
        acc.x = fmaxf(acc.x, 0.f); acc.y = fmaxf(acc.y, 0.f);
        acc.z = fmaxf(acc.z, 0.f); acc.w = fmaxf(acc.w, 0.f);
    }
    __half2 o0 = __floats2half2_rn(acc.x, acc.y);
    __half2 o1 = __floats2half2_rn(acc.z, acc.w);
    *(uint2*)(outh + (size_t)wrp * FD + lane * 4) =
        make_uint2(*(uint32_t*)&o0, *(uint32_t*)&o1);
}

// ===== batched fused hop-agg + bilinear score: cols 10 (good), 11 (bad) =====
__global__ void k_aggscore2(const __half* __restrict__ G, size_t hShiftB,
                            const __half* __restrict__ T,
                            const int* __restrict__ off, const int* __restrict__ ssrc,
                            const float* __restrict__ sw, const float* __restrict__ invd,
                            const float* __restrict__ b3, float* __restrict__ out)
{
    const unsigned FULL = 0xffffffffu;
    int wrp = (blockIdx.x * blockDim.x + threadIdx.x) >> 5;
    int lane = threadIdx.x & 31;
    if (wrp >= 2 * NN) return;
    int part = (wrp >= NN);
    int node = wrp - part * NN;
    const __half* Gb = G + (part ? hShiftB : 0);

    uint2 tr = *(const uint2*)(T + (size_t)node * FD + lane * 4);
    float2 t0 = __half22float2(*(__half2*)&tr.x);
    float2 t1 = __half22float2(*(__half2*)&tr.y);
    int s = off[node], e = off[node + 1];
    float acc = 0.f;
    for (int i = s; i < e; i++) {
        int   src = ssrc[i];
        float w   = sw[i];
        uint2 raw = *(const uint2*)(Gb + (size_t)src * FD + lane * 4);
        float2 f0 = __half22float2(*(__half2*)&raw.x);
        float2 f1 = __half22float2(*(__half2*)&raw.y);
        acc = fmaf(w, t0.x * f0.x + t0.y * f0.y + t1.x * f1.x + t1.y * f1.y, acc);
    }
    uint2 rs = *(const uint2*)(Gb + (size_t)node * FD + lane * 4);
    float2 s0 = __half22float2(*(__half2*)&rs.x);
    float2 s1 = __half22float2(*(__half2*)&rs.y);
    float4 bb = *(const float4*)(b3 + lane * 4);
    acc = fmaf(invd[node], t0.x * s0.x + t0.y * s0.y + t1.x * s1.x + t1.y * s1.y, acc);
    acc += t0.x * bb.x + t0.y * bb.y + t1.x * bb.z + t1.y * bb.w;
    #pragma unroll
    for (int d = 16; d > 0; d >>= 1) acc += __shfl_xor_sync(FULL, acc, d);
    if (lane == 0)
        out[(size_t)node * OUTC + 10 + part] = 1.0f / (1.0f + expf(-acc));
}

// ================= classifier =================
__global__ void k_gemm10(const __half* __restrict__ A, const float* __restrict__ W,
                         float* __restrict__ C)
{
    __shared__ float w[FD * NC];
    for (int i = threadIdx.x; i < FD * NC; i += blockDim.x) w[i] = W[i];
    __syncthreads();
    int r = blockIdx.x * blockDim.x + threadIdx.x;
    if (r >= NN) return;
    float acc[NC];
    #pragma unroll
    for (int j = 0; j < NC; j++) acc[j] = 0.f;
    const uint4* ap = (const uint4*)(A + (size_t)r * FD);
    #pragma unroll 4
    for (int k8 = 0; k8 < 16; k8++) {
        uint4 u = ap[k8];
        const __half2* hp = (const __half2*)&u;
        float2 f0 = __half22float2(hp[0]);
        float2 f1 = __half22float2(hp[1]);
        float2 f2 = __half22float2(hp[2]);
        float2 f3 = __half22float2(hp[3]);
        int k = k8 * 8;
        #pragma unroll
        for (int j = 0; j < NC; j++) {
            acc[j] = fmaf(f0.x, w[(k + 0) * NC + j], acc[j]);
            acc[j] = fmaf(f0.y, w[(k + 1) * NC + j], acc[j]);
            acc[j] = fmaf(f1.x, w[(k + 2) * NC + j], acc[j]);
            acc[j] = fmaf(f1.y, w[(k + 3) * NC + j], acc[j]);
            acc[j] = fmaf(f2.x, w[(k + 4) * NC + j], acc[j]);
            acc[j] = fmaf(f2.y, w[(k + 5) * NC + j], acc[j]);
            acc[j] = fmaf(f3.x, w[(k + 6) * NC + j], acc[j]);
            acc[j] = fmaf(f3.y, w[(k + 7) * NC + j], acc[j]);
        }
    }
    #pragma unroll
    for (int j = 0; j < NC; j++) C[(size_t)r * NC + j] = acc[j];
}

__global__ void k_agg10(const float* __restrict__ h, const int* __restrict__ off,
                        const int* __restrict__ ssrc, const float* __restrict__ sw,
                        const float* __restrict__ invd, const float* __restrict__ bc,
                        float* __restrict__ out)
{
    int node = (blockIdx.x * blockDim.x + threadIdx.x) >> 5;
    int lane = threadIdx.x & 31;
    if (node >= NN || lane >= NC) return;
    int s = off[node], e = off[node + 1];
    float acc = 0.f;
    for (int i = s; i < e; i++) {
        int src = ssrc[i];
        acc = fmaf(sw[i], h[(size_t)src * NC + lane], acc);
    }
    acc = fmaf(invd[node], h[(size_t)node * NC + lane], acc) + bc[lane];
    out[(size_t)node * OUTC + lane] = acc;
}

// ================= host =================
extern "C" void kernel_launch(void* const* d_in, const int* in_sizes, int n_in,
                              void* d_out, int out_size)
{
    const float* x    = (const float*)d_in[0];
    const int*   ei   = (const int*)  d_in[1];
    const int*   eh   = (const int*)  d_in[2];
    const int*   perm = (const int*)  d_in[4];
    const float* W1   = (const float*)d_in[5];
    const float* b1   = (const float*)d_in[6];
    const float* W2   = (const float*)d_in[7];
    const float* b2   = (const float*)d_in[8];
    const float* W3   = (const float*)d_in[9];
    const float* b3   = (const float*)d_in[10];
    const float* M1   = (const float*)d_in[11];
    const float* mb1  = (const float*)d_in[12];
    const float* M2   = (const float*)d_in[13];
    const float* mb2  = (const float*)d_in[14];
    const float* Wc   = (const float*)d_in[15];
    const float* bc   = (const float*)d_in[16];
    const float* Wd   = (const float*)d_in[17];
    float* out = (float*)d_out;

    float *C10, *dis, *invd, *sw;
    __half *Hh, *P1, *Gh, *P2, *Th, *Wf;
    int *cnt, *off, *cur, *btot, *ssrc, *ssrcp;
    cudaGetSymbolAddress((void**)&Hh,   g_Hh);
    cudaGetSymbolAddress((void**)&P1,   g_P1);
    cudaGetSymbolAddress((void**)&Gh,   g_Gh);
    cudaGetSymbolAddress((void**)&P2,   g_P2);
    cudaGetSymbolAddress((void**)&Th,   g_Th);
    cudaGetSymbolAddress((void**)&C10,  g_C10);
    cudaGetSymbolAddress((void**)&Wf,   g_Wf);
    cudaGetSymbolAddress((void**)&cnt,  g_cnt);
    cudaGetSymbolAddress((void**)&dis,  g_dis);
    cudaGetSymbolAddress((void**)&invd, g_invd);
    cudaGetSymbolAddress((void**)&off,  g_off);
    cudaGetSymbolAddress((void**)&cur,  g_cur);
    cudaGetSymbolAddress((void**)&btot, g_btot);
    cudaGetSymbolAddress((void**)&ssrc, g_ssrc);
    cudaGetSymbolAddress((void**)&ssrcp,g_ssrcp);
    cudaGetSymbolAddress((void**)&sw,   g_sw);

    cudaFuncSetAttribute(k_wmma,  cudaFuncAttributeMaxDynamicSharedMemorySize, SMEM_SZ);
    cudaFuncSetAttribute(k_wmmaX, cudaFuncAttributeMaxDynamicSharedMemorySize, XSMEM);
    cudaFuncSetAttribute(k_wmma3, cudaFuncAttributeMaxDynamicSharedMemorySize, W3_SMEM);

    const int TE  = 256;
    const int GN  = (NN + TE - 1) / TE;
    const int GE2 = (2 * NE + TE - 1) / TE;
    const int GW  = (NN * 32 + TE - 1) / TE;
    const int GW2 = (2 * NN * 32 + TE - 1) / TE;
    const int GM  = (NN + 127) / 128;
    const int GM2 = (2 * NN + 127) / 128;
    const size_t HB = (size_t)NN * FD;

    // ---- prologue (node 5 = k_wmmaX for ncu) ----
    cudaMemsetAsync(cnt, 0, sizeof(int) * 2 * NN);
    k_count2<<<GE2, TE>>>(ei + NE, eh + NE, cnt);
    k_prepw<<<(512 * 128 + 255) / 256, 256>>>(W1, Wf + WOFF_W1, 512);
    k_deg2<<<(2 * NN + TE - 1) / TE, TE>>>(cnt, dis, invd);
    k_wmmaX<<<GM, 256, XSMEM>>>(x, Wf + WOFF_W1, nullptr, 0, Hh, NN, 512);

    // ---- scans + placement ----
    k_scan_blk2<<<2 * NB, SCB>>>(cnt, off, btot);
    k_scan_tot2<<<2, 128>>>(btot, off);
    k_scan_add2<<<2 * GN, TE>>>(off, btot, cur, GN);
    k_place2<<<GE2, TE>>>(ei, eh, dis, cur, ssrc, sw, perm, ssrcp);
    k_prepw5<<<(5 * 128 * 128 + 255) / 256, 256>>>(W2, W3, M1, M2, Wd, Wf);

    // ---- layer1 batched agg (Hh for both halves) -> P1[2NN] ----
    k_agg2<<<GW2, TE>>>(Hh, 0, ssrc, ssrcp, perm, off, sw, invd, b1, P1, 1);

    // ---- batched W2 GEMM -> Gh[2NN] ----
    k_wmma<<<GM2, 256, SMEM_SZ>>>(P1, Wf + WOFF_W2, nullptr, 0, Gh, 2 * NN, 128);

    // ---- layer2 batched agg (Gh halves) -> P2[2NN] ----
    k_agg2<<<GW2, TE>>>(Gh, HB, ssrc, ssrc, nullptr, off, sw, invd, b2, P2, 1);

    // ---- fused MLP+discriminator: Th = ((relu(P2@M1+mb1))@M2+mb2)@Wd ----
    k_wmma3<<<GM, 256, W3_SMEM>>>(P2, Wf + WOFF_M1, Wf + WOFF_M2, Wf + WOFF_WD,
                                  mb1, mb2, Th, NN);

    // ---- classifier ----
    k_gemm10<<<GN, TE>>>(P2, Wc, C10);
    k_agg10<<<GW, TE>>>(C10, off, ssrc, sw, invd, bc, out);

    // ---- batched W3 GEMM (P2 -> P1 reuse) + batched score ----
    k_wmma<<<GM2, 256, SMEM_SZ>>>(P2, Wf + WOFF_W3, nullptr, 0, P1, 2 * NN, 128);
    k_aggscore2<<<GW2, TE>>>(P1, HB, Th, off + (NN + 1), ssrc + NE, sw + NE,
                             invd + NN, b3, out);
}